// round 2
// baseline (speedup 1.0000x reference)
#include <cuda_runtime.h>

#define B_    4
#define C_    32
#define H_    128
#define W_    256
#define CR_   85
#define HW_   (H_*W_)        // 32768
#define CHW_  (C_*HW_)       // 1048576
#define WW_   (W_*W_)        // 65536
#define BHWW_ (B_*H_*WW_)    // 33554432
#define XN_   (B_*CHW_)      // 4194304
#define STR_  34             // padded row stride for smem q/k

// ---- packed f32x2 helpers (Blackwell sm_103a) ----
__device__ __forceinline__ unsigned long long pack2(float lo, float hi) {
    unsigned long long r;
    asm("mov.b64 %0, {%1, %2};" : "=l"(r) : "f"(lo), "f"(hi));
    return r;
}
__device__ __forceinline__ void fma2(unsigned long long &d, unsigned long long a, unsigned long long b) {
    asm("fma.rn.f32x2 %0, %1, %2, %0;" : "+l"(d) : "l"(a), "l"(b));
}
__device__ __forceinline__ unsigned long long add2(unsigned long long a, unsigned long long b) {
    unsigned long long r;
    asm("add.rn.f32x2 %0, %1, %2;" : "=l"(r) : "l"(a), "l"(b));
    return r;
}
__device__ __forceinline__ float sum2(unsigned long long a) {
    float lo, hi;
    asm("mov.b64 {%0, %1}, %2;" : "=f"(lo), "=f"(hi) : "l"(a));
    return lo + hi;
}

// One block = (b, h, direction). d=0: r2l (q from left, k from right, lower band).
//                                d=1: l2r (q from right, k from left, upper band).
extern "C" __global__ void __launch_bounds__(256, 2)
pab_kernel(const float* __restrict__ x_left, const float* __restrict__ x_right,
           const float* __restrict__ cost,
           const float* __restrict__ qw, const float* __restrict__ qb,
           const float* __restrict__ qg, const float* __restrict__ qbe,
           const float* __restrict__ qm, const float* __restrict__ qv,
           const float* __restrict__ kw, const float* __restrict__ kb,
           const float* __restrict__ kg, const float* __restrict__ kbe,
           const float* __restrict__ km, const float* __restrict__ kv,
           float* __restrict__ out)
{
    extern __shared__ float sm[];
    float* qA  = sm;                    // [256][34]
    float* kA  = sm + 256 * STR_;       // [256][34]
    float* wqs = sm + 2 * 256 * STR_;   // [32][32] BN-folded q weights
    float* wks = wqs + 1024;            // [32][32] BN-folded k weights
    float* bqs = wks + 1024;            // [32]
    float* bks = bqs + 32;              // [32]

    const int tid = threadIdx.x;
    const int bx  = blockIdx.x;
    const int d   = bx & 1;
    const int bh  = bx >> 1;
    const int b   = bh >> 7;
    const int h   = bh & 127;

    // ---- fold BatchNorm into conv weights/bias ----
    for (int t = tid; t < 1024; t += 256) {
        const int o = t >> 5;
        const float sq = qg[o] * rsqrtf(qv[o] + 1e-5f);
        const float sk = kg[o] * rsqrtf(kv[o] + 1e-5f);
        wqs[t] = qw[t] * sq;
        wks[t] = kw[t] * sk;
    }
    if (tid < 32) {
        const float sq = qg[tid] * rsqrtf(qv[tid] + 1e-5f);
        const float sk = kg[tid] * rsqrtf(kv[tid] + 1e-5f);
        bqs[tid] = qb[tid] * sq + qbe[tid] - qm[tid] * sq;
        bks[tid] = kb[tid] * sk + kbe[tid] - km[tid] * sk;
    }
    __syncthreads();

    // ---- projections: this block needs q(sideQ) and k(sideK) ----
    {
        const int i = tid;  // pixel along W
        const long base = (long)b * CHW_ + (long)h * W_ + i;
        const float* xq = (d ? x_right : x_left) + base;
        const float* xk = (d ? x_left  : x_right) + base;

        // q side (also emit the x*2 passthrough for this side's image)
        {
            float xv[32];
            #pragma unroll
            for (int c = 0; c < 32; c++) xv[c] = xq[(long)c * HW_];
            float* ox = out + (d ? XN_ : 0) + base;
            #pragma unroll
            for (int c = 0; c < 32; c++) ox[(long)c * HW_] = 2.0f * xv[c];
            unsigned long long x2[16];
            #pragma unroll
            for (int c2 = 0; c2 < 16; c2++) x2[c2] = pack2(xv[2*c2], xv[2*c2+1]);
            #pragma unroll
            for (int o = 0; o < 32; o++) {
                unsigned long long a0 = 0ull, a1 = 0ull;
                const unsigned long long* wr = (const unsigned long long*)(wqs + o * 32);
                #pragma unroll
                for (int c2 = 0; c2 < 16; c2 += 2) {
                    fma2(a0, wr[c2],   x2[c2]);
                    fma2(a1, wr[c2+1], x2[c2+1]);
                }
                qA[i * STR_ + o] = sum2(add2(a0, a1)) + bqs[o];
            }
        }
        // k side
        {
            float xv[32];
            #pragma unroll
            for (int c = 0; c < 32; c++) xv[c] = xk[(long)c * HW_];
            unsigned long long x2[16];
            #pragma unroll
            for (int c2 = 0; c2 < 16; c2++) x2[c2] = pack2(xv[2*c2], xv[2*c2+1]);
            #pragma unroll
            for (int o = 0; o < 32; o++) {
                unsigned long long a0 = 0ull, a1 = 0ull;
                const unsigned long long* wr = (const unsigned long long*)(wks + o * 32);
                #pragma unroll
                for (int c2 = 0; c2 < 16; c2 += 2) {
                    fma2(a0, wr[c2],   x2[c2]);
                    fma2(a1, wr[c2+1], x2[c2+1]);
                }
                kA[i * STR_ + o] = sum2(add2(a0, a1)) + bks[o];
            }
        }
    }
    __syncthreads();

    // ---- banded attention + cost stream ----
    const int warp = tid >> 5;
    const int lane = tid & 31;
    const float inv_c = 1.0f / 32.0f;
    const float* cbase = cost + (size_t)d * BHWW_ + (size_t)(b * H_ + h) * WW_;
    float*       obase = out  + (d ? (2*XN_ + BHWW_) : (2*XN_)) + (size_t)(b * H_ + h) * WW_;

    // 64 tile jobs (8x8 grid of 32x32 tiles), 8 per warp: warp w owns i-tile w.
    #pragma unroll 1
    for (int n = 0; n < 8; n++) {
        const int it = warp;
        const int jt = n;
        const int delta = d ? (jt - it) : (it - jt);
        const int jj = jt * 32 + lane;
        const float* cp = cbase + (size_t)(it * 32) * W_ + jj;
        float*       op = obase + (size_t)(it * 32) * W_ + jj;

        if (delta >= 0 && delta <= 3) {
            // compute tile: lane caches its k row in registers, reused over 32 i's
            unsigned long long k2[16];
            const unsigned long long* krow = (const unsigned long long*)(kA + jj * STR_);
            #pragma unroll
            for (int c2 = 0; c2 < 16; c2++) k2[c2] = krow[c2];

            float cv = __ldg(cp);
            #pragma unroll 4
            for (int i = 0; i < 32; i++) {
                const float cur = cv;
                if (i < 31) cv = __ldg(cp + (size_t)(i + 1) * W_);
                const int ii = it * 32 + i;
                const unsigned long long* qrow = (const unsigned long long*)(qA + ii * STR_);
                unsigned long long a0 = 0ull, a1 = 0ull, a2 = 0ull, a3 = 0ull;
                #pragma unroll
                for (int c2 = 0; c2 < 16; c2 += 4) {
                    fma2(a0, qrow[c2],   k2[c2]);
                    fma2(a1, qrow[c2+1], k2[c2+1]);
                    fma2(a2, qrow[c2+2], k2[c2+2]);
                    fma2(a3, qrow[c2+3], k2[c2+3]);
                }
                const float s = sum2(add2(add2(a0, a1), add2(a2, a3))) * inv_c;
                const int diff = d ? (jj - ii) : (ii - jj);
                op[(size_t)i * W_] = ((unsigned)diff < (unsigned)CR_) ? (cur + s) : cur;
            }
        } else {
            // pure copy tile, 4-way batched for MLP
            #pragma unroll
            for (int i = 0; i < 32; i += 4) {
                const float v0 = __ldg(cp + (size_t)(i + 0) * W_);
                const float v1 = __ldg(cp + (size_t)(i + 1) * W_);
                const float v2 = __ldg(cp + (size_t)(i + 2) * W_);
                const float v3 = __ldg(cp + (size_t)(i + 3) * W_);
                op[(size_t)(i + 0) * W_] = v0;
                op[(size_t)(i + 1) * W_] = v1;
                op[(size_t)(i + 2) * W_] = v2;
                op[(size_t)(i + 3) * W_] = v3;
            }
        }
    }
}

extern "C" void kernel_launch(void* const* d_in, const int* in_sizes, int n_in,
                              void* d_out, int out_size)
{
    (void)in_sizes; (void)n_in; (void)out_size;
    const int smem_bytes = (2 * 256 * STR_ + 2 * 1024 + 64) * sizeof(float);  // 78080
    cudaFuncSetAttribute(pab_kernel, cudaFuncAttributeMaxDynamicSharedMemorySize, smem_bytes);
    pab_kernel<<<2 * B_ * H_, 256, smem_bytes>>>(
        (const float*)d_in[0],  (const float*)d_in[1],  (const float*)d_in[2],
        (const float*)d_in[3],  (const float*)d_in[4],  (const float*)d_in[5],
        (const float*)d_in[6],  (const float*)d_in[7],  (const float*)d_in[8],
        (const float*)d_in[9],  (const float*)d_in[10], (const float*)d_in[11],
        (const float*)d_in[12], (const float*)d_in[13], (const float*)d_in[14],
        (float*)d_out);
}

// round 3
// speedup vs baseline: 1.0710x; 1.0710x over previous
#include <cuda_runtime.h>

#define B_    4
#define C_    32
#define H_    128
#define W_    256
#define CR_   85
#define HW_   (H_*W_)        // 32768
#define CHW_  (C_*HW_)       // 1048576
#define WW_   (W_*W_)        // 65536
#define BHWW_ (B_*H_*WW_)    // 33554432
#define XN_   (B_*CHW_)      // 4194304
#define STR_  34             // padded row stride for smem q/k

// Tile schedule (d=0 orientation; swap it/jt for d=1).
// Compute tiles: it-jt in [0,3]  (26 tiles). Copy tiles: the rest (38).
__constant__ unsigned char CTILE[26] = {
    0, 9, 18, 27, 36, 45, 54, 63,      // delta 0
    8, 17, 26, 35, 44, 53, 62,         // delta 1
    16, 25, 34, 43, 52, 61,            // delta 2
    24, 33, 42, 51, 60                 // delta 3
};
__constant__ unsigned char CPTILE[38] = {
    1, 2, 3, 4, 5, 6, 7,
    10, 11, 12, 13, 14, 15,
    19, 20, 21, 22, 23,
    28, 29, 30, 31,
    32, 37, 38, 39,
    40, 41, 46, 47,
    48, 49, 50, 55,
    56, 57, 58, 59
};

// ---- packed f32x2 helpers (Blackwell sm_103a) ----
__device__ __forceinline__ unsigned long long pack2(float lo, float hi) {
    unsigned long long r;
    asm("mov.b64 %0, {%1, %2};" : "=l"(r) : "f"(lo), "f"(hi));
    return r;
}
__device__ __forceinline__ void fma2(unsigned long long &d, unsigned long long a, unsigned long long b) {
    asm("fma.rn.f32x2 %0, %1, %2, %0;" : "+l"(d) : "l"(a), "l"(b));
}
__device__ __forceinline__ unsigned long long add2(unsigned long long a, unsigned long long b) {
    unsigned long long r;
    asm("add.rn.f32x2 %0, %1, %2;" : "=l"(r) : "l"(a), "l"(b));
    return r;
}
__device__ __forceinline__ float sum2(unsigned long long a) {
    float lo, hi;
    asm("mov.b64 {%0, %1}, %2;" : "=f"(lo), "=f"(hi) : "l"(a));
    return lo + hi;
}

extern "C" __global__ void __launch_bounds__(256, 2)
pab_kernel(const float* __restrict__ x_left, const float* __restrict__ x_right,
           const float* __restrict__ cost,
           const float* __restrict__ qw, const float* __restrict__ qb,
           const float* __restrict__ qg, const float* __restrict__ qbe,
           const float* __restrict__ qm, const float* __restrict__ qv,
           const float* __restrict__ kw, const float* __restrict__ kb,
           const float* __restrict__ kg, const float* __restrict__ kbe,
           const float* __restrict__ km, const float* __restrict__ kv,
           float* __restrict__ out)
{
    extern __shared__ float sm[];
    float* qA  = sm;                    // [256][34]
    float* kA  = sm + 256 * STR_;       // [256][34]
    float* wqs = sm + 2 * 256 * STR_;   // [32][32] BN-folded q weights
    float* wks = wqs + 1024;            // [32][32] BN-folded k weights
    float* bqs = wks + 1024;            // [32]
    float* bks = bqs + 32;              // [32]
    float* scoreB = wqs;                // reused after projection: 8 warps x 256 floats

    const int tid = threadIdx.x;
    const int bx  = blockIdx.x;
    const int d   = bx & 1;
    const int bh  = bx >> 1;
    const int b   = bh >> 7;
    const int h   = bh & 127;

    // ---- fold BatchNorm into conv weights/bias ----
    for (int t = tid; t < 1024; t += 256) {
        const int o = t >> 5;
        const float sq = qg[o] * rsqrtf(qv[o] + 1e-5f);
        const float sk = kg[o] * rsqrtf(kv[o] + 1e-5f);
        wqs[t] = qw[t] * sq;
        wks[t] = kw[t] * sk;
    }
    if (tid < 32) {
        const float sq = qg[tid] * rsqrtf(qv[tid] + 1e-5f);
        const float sk = kg[tid] * rsqrtf(kv[tid] + 1e-5f);
        bqs[tid] = qb[tid] * sq + qbe[tid] - qm[tid] * sq;
        bks[tid] = kb[tid] * sk + kbe[tid] - km[tid] * sk;
    }
    __syncthreads();

    // ---- projections ----
    {
        const int i = tid;
        const long base = (long)b * CHW_ + (long)h * W_ + i;
        const float* xq = (d ? x_right : x_left) + base;
        const float* xk = (d ? x_left  : x_right) + base;

        {
            float xv[32];
            #pragma unroll
            for (int c = 0; c < 32; c++) xv[c] = xq[(long)c * HW_];
            float* ox = out + (d ? XN_ : 0) + base;
            #pragma unroll
            for (int c = 0; c < 32; c++) ox[(long)c * HW_] = 2.0f * xv[c];
            unsigned long long x2[16];
            #pragma unroll
            for (int c2 = 0; c2 < 16; c2++) x2[c2] = pack2(xv[2*c2], xv[2*c2+1]);
            #pragma unroll
            for (int o = 0; o < 32; o++) {
                unsigned long long a0 = 0ull, a1 = 0ull;
                const unsigned long long* wr = (const unsigned long long*)(wqs + o * 32);
                #pragma unroll
                for (int c2 = 0; c2 < 16; c2 += 2) {
                    fma2(a0, wr[c2],   x2[c2]);
                    fma2(a1, wr[c2+1], x2[c2+1]);
                }
                qA[i * STR_ + o] = sum2(add2(a0, a1)) + bqs[o];
            }
        }
        {
            float xv[32];
            #pragma unroll
            for (int c = 0; c < 32; c++) xv[c] = xk[(long)c * HW_];
            unsigned long long x2[16];
            #pragma unroll
            for (int c2 = 0; c2 < 16; c2++) x2[c2] = pack2(xv[2*c2], xv[2*c2+1]);
            #pragma unroll
            for (int o = 0; o < 32; o++) {
                unsigned long long a0 = 0ull, a1 = 0ull;
                const unsigned long long* wr = (const unsigned long long*)(wks + o * 32);
                #pragma unroll
                for (int c2 = 0; c2 < 16; c2 += 2) {
                    fma2(a0, wr[c2],   x2[c2]);
                    fma2(a1, wr[c2+1], x2[c2+1]);
                }
                kA[i * STR_ + o] = sum2(add2(a0, a1)) + bks[o];
            }
        }
    }
    __syncthreads();

    // ---- banded attention + cost stream ----
    const int warp = tid >> 5;
    const int lane = tid & 31;
    const float inv_c = 1.0f / 32.0f;
    const float* cbase = cost + (size_t)d * BHWW_ + (size_t)(b * H_ + h) * WW_;
    float*       obase = out  + (d ? (2*XN_ + BHWW_) : (2*XN_)) + (size_t)(b * H_ + h) * WW_;

    const int r0 = lane >> 3;           // 0..3
    const int c4 = (lane & 7) << 2;     // 0,4,...,28
    float* sw = scoreB + warp * 256;    // per-warp swizzled score chunk [8][32]

    #pragma unroll 1
    for (int n = 0; n < 8; n++) {
        const int t = warp + (n << 3);
        const int code = (t < 26) ? CTILE[t] : CPTILE[t - 26];
        int it = code >> 3, jt = code & 7;
        if (d) { const int tmp = it; it = jt; jt = tmp; }
        const float* cpt = cbase + (size_t)(it * 32) * W_ + jt * 32;
        float*       opt = obase + (size_t)(it * 32) * W_ + jt * 32;

        if (t < 26) {
            // ---- compute tile ----
            const int jj = jt * 32 + lane;
            unsigned long long k2[16];
            const unsigned long long* krow = (const unsigned long long*)(kA + jj * STR_);
            #pragma unroll
            for (int c2 = 0; c2 < 16; c2++) k2[c2] = krow[c2];

            float4 cv0 = __ldcs((const float4*)(cpt + (size_t)r0 * W_ + c4));
            float4 cv1 = __ldcs((const float4*)(cpt + (size_t)(r0 + 4) * W_ + c4));

            #pragma unroll
            for (int cc = 0; cc < 4; cc++) {
                // compute 8 rows of scores into swizzled smem
                #pragma unroll
                for (int rr = 0; rr < 8; rr++) {
                    const int ii = it * 32 + (cc << 3) + rr;
                    const unsigned long long* qrow = (const unsigned long long*)(qA + ii * STR_);
                    unsigned long long a0 = 0ull, a1 = 0ull, a2 = 0ull, a3 = 0ull;
                    #pragma unroll
                    for (int c2 = 0; c2 < 16; c2 += 4) {
                        fma2(a0, qrow[c2],   k2[c2]);
                        fma2(a1, qrow[c2+1], k2[c2+1]);
                        fma2(a2, qrow[c2+2], k2[c2+2]);
                        fma2(a3, qrow[c2+3], k2[c2+3]);
                    }
                    const float s = sum2(add2(add2(a0, a1), add2(a2, a3))) * inv_c;
                    const int diff = d ? (jj - ii) : (ii - jj);
                    const float sv = ((unsigned)diff < (unsigned)CR_) ? s : 0.0f;
                    // swizzled store: f4-block (lane>>2) XOR row
                    sw[(rr << 5) + ((((lane >> 2) ^ rr) & 7) << 2) + (lane & 3)] = sv;
                }
                __syncwarp();
                const float4 s0 = *(const float4*)(sw + (r0 << 5) + ((((lane & 7) ^ r0) & 7) << 2));
                const float4 s1 = *(const float4*)(sw + ((r0 + 4) << 5) + ((((lane & 7) ^ (r0 + 4)) & 7) << 2));
                __syncwarp();

                const int ra = (cc << 3) + r0;
                const int rb = ra + 4;
                float4 n0 = cv0, n1 = cv1;
                if (cc < 3) {
                    n0 = __ldcs((const float4*)(cpt + (size_t)(ra + 8) * W_ + c4));
                    n1 = __ldcs((const float4*)(cpt + (size_t)(rb + 8) * W_ + c4));
                }
                float4 o0, o1;
                o0.x = cv0.x + s0.x; o0.y = cv0.y + s0.y; o0.z = cv0.z + s0.z; o0.w = cv0.w + s0.w;
                o1.x = cv1.x + s1.x; o1.y = cv1.y + s1.y; o1.z = cv1.z + s1.z; o1.w = cv1.w + s1.w;
                __stcs((float4*)(opt + (size_t)ra * W_ + c4), o0);
                __stcs((float4*)(opt + (size_t)rb * W_ + c4), o1);
                cv0 = n0; cv1 = n1;
            }
        } else {
            // ---- pure copy tile: 8 LDG.128 in flight per lane ----
            float4 v[8];
            #pragma unroll
            for (int tt = 0; tt < 8; tt++)
                v[tt] = __ldcs((const float4*)(cpt + (size_t)((tt << 2) + r0) * W_ + c4));
            #pragma unroll
            for (int tt = 0; tt < 8; tt++)
                __stcs((float4*)(opt + (size_t)((tt << 2) + r0) * W_ + c4), v[tt]);
        }
    }
}

extern "C" void kernel_launch(void* const* d_in, const int* in_sizes, int n_in,
                              void* d_out, int out_size)
{
    (void)in_sizes; (void)n_in; (void)out_size;
    const int smem_bytes = (2 * 256 * STR_ + 2 * 1024 + 64) * sizeof(float);  // 78080
    cudaFuncSetAttribute(pab_kernel, cudaFuncAttributeMaxDynamicSharedMemorySize, smem_bytes);
    pab_kernel<<<2 * B_ * H_, 256, smem_bytes>>>(
        (const float*)d_in[0],  (const float*)d_in[1],  (const float*)d_in[2],
        (const float*)d_in[3],  (const float*)d_in[4],  (const float*)d_in[5],
        (const float*)d_in[6],  (const float*)d_in[7],  (const float*)d_in[8],
        (const float*)d_in[9],  (const float*)d_in[10], (const float*)d_in[11],
        (const float*)d_in[12], (const float*)d_in[13], (const float*)d_in[14],
        (float*)d_out);
}

// round 7
// speedup vs baseline: 1.0892x; 1.0170x over previous
#include <cuda_runtime.h>

#define B_    4
#define C_    32
#define H_    128
#define W_    256
#define CR_   85
#define HW_   (H_*W_)        // 32768
#define CHW_  (C_*HW_)       // 1048576
#define WW_   (W_*W_)        // 65536
#define BHWW_ (B_*H_*WW_)    // 33554432
#define XN_   (B_*CHW_)      // 4194304
#define STR_  34             // padded row stride for smem q/k

// Per-warp interleaved schedule: SCHED[w*8+n] = tile_code (it*8+jt, d=0 frame)
// | 0x80 if compute tile. Even warps compute on odd n, odd warps on even n:
// at every n (0..5) exactly 4 warps compute + 4 copy -> flat DRAM demand.
__constant__ unsigned char SCHED[64] = {
    //  n=0     n=1     n=2     n=3     n=4     n=5     n=6     n=7
       1,   128+0,     2,   128+9,     3,  128+18,     4,  128+27,   // w0
    128+36,     5,  128+45,     6,  128+54,     7,  128+63,    10,   // w1
      11,   128+8,    12,  128+17,    13,  128+26,    14,    15,     // w2
    128+35,    19,  128+44,    20,  128+53,    21,    22,    23,     // w3
      28,  128+62,    29,  128+16,    30,  128+25,    31,    32,     // w4
    128+34,    37,  128+43,    38,  128+52,    39,    40,    41,     // w5
      46,  128+61,    47,  128+24,    48,  128+33,    49,    50,     // w6
    128+42,    55,  128+51,    56,  128+60,    57,    58,    59      // w7
};

// ---- packed f32x2 helpers (Blackwell sm_103a) ----
__device__ __forceinline__ unsigned long long pack2(float lo, float hi) {
    unsigned long long r;
    asm("mov.b64 %0, {%1, %2};" : "=l"(r) : "f"(lo), "f"(hi));
    return r;
}
__device__ __forceinline__ void fma2(unsigned long long &d, unsigned long long a, unsigned long long b) {
    asm("fma.rn.f32x2 %0, %1, %2, %0;" : "+l"(d) : "l"(a), "l"(b));
}
__device__ __forceinline__ unsigned long long add2(unsigned long long a, unsigned long long b) {
    unsigned long long r;
    asm("add.rn.f32x2 %0, %1, %2;" : "=l"(r) : "l"(a), "l"(b));
    return r;
}
__device__ __forceinline__ float sum2(unsigned long long a) {
    float lo, hi;
    asm("mov.b64 {%0, %1}, %2;" : "=f"(lo), "=f"(hi) : "l"(a));
    return lo + hi;
}

extern "C" __global__ void __launch_bounds__(256, 2)
pab_kernel(const float* __restrict__ x_left, const float* __restrict__ x_right,
           const float* __restrict__ cost,
           const float* __restrict__ qw, const float* __restrict__ qb,
           const float* __restrict__ qg, const float* __restrict__ qbe,
           const float* __restrict__ qm, const float* __restrict__ qv,
           const float* __restrict__ kw, const float* __restrict__ kb,
           const float* __restrict__ kg, const float* __restrict__ kbe,
           const float* __restrict__ km, const float* __restrict__ kv,
           float* __restrict__ out)
{
    extern __shared__ float sm[];
    float* qA  = sm;                    // [256][34]
    float* kA  = sm + 256 * STR_;       // [256][34]
    float* wqs = sm + 2 * 256 * STR_;   // [32][32] BN-folded q weights
    float* wks = wqs + 1024;            // [32][32] BN-folded k weights
    float* bqs = wks + 1024;            // [32]
    float* bks = bqs + 32;              // [32]
    float* scoreB = wqs;                // reused after projection: 8 warps x 256 floats

    const int tid = threadIdx.x;
    const int bx  = blockIdx.x;
    const int d   = bx & 1;
    const int bh  = bx >> 1;
    const int b   = bh >> 7;
    const int h   = bh & 127;

    // ---- fold BatchNorm into conv weights/bias ----
    for (int t = tid; t < 1024; t += 256) {
        const int o = t >> 5;
        const float sq = qg[o] * rsqrtf(qv[o] + 1e-5f);
        const float sk = kg[o] * rsqrtf(kv[o] + 1e-5f);
        wqs[t] = qw[t] * sq;
        wks[t] = kw[t] * sk;
    }
    if (tid < 32) {
        const float sq = qg[tid] * rsqrtf(qv[tid] + 1e-5f);
        const float sk = kg[tid] * rsqrtf(kv[tid] + 1e-5f);
        bqs[tid] = qb[tid] * sq + qbe[tid] - qm[tid] * sq;
        bks[tid] = kb[tid] * sk + kbe[tid] - km[tid] * sk;
    }
    __syncthreads();

    // ---- projections ----
    {
        const int i = tid;
        const long base = (long)b * CHW_ + (long)h * W_ + i;
        const float* xq = (d ? x_right : x_left) + base;
        const float* xk = (d ? x_left  : x_right) + base;

        {
            float xv[32];
            #pragma unroll
            for (int c = 0; c < 32; c++) xv[c] = xq[(long)c * HW_];
            float* ox = out + (d ? XN_ : 0) + base;
            #pragma unroll
            for (int c = 0; c < 32; c++) ox[(long)c * HW_] = 2.0f * xv[c];
            unsigned long long x2[16];
            #pragma unroll
            for (int c2 = 0; c2 < 16; c2++) x2[c2] = pack2(xv[2*c2], xv[2*c2+1]);
            #pragma unroll
            for (int o = 0; o < 32; o++) {
                unsigned long long a0 = 0ull, a1 = 0ull;
                const unsigned long long* wr = (const unsigned long long*)(wqs + o * 32);
                #pragma unroll
                for (int c2 = 0; c2 < 16; c2 += 2) {
                    fma2(a0, wr[c2],   x2[c2]);
                    fma2(a1, wr[c2+1], x2[c2+1]);
                }
                qA[i * STR_ + o] = sum2(add2(a0, a1)) + bqs[o];
            }
        }
        {
            float xv[32];
            #pragma unroll
            for (int c = 0; c < 32; c++) xv[c] = xk[(long)c * HW_];
            unsigned long long x2[16];
            #pragma unroll
            for (int c2 = 0; c2 < 16; c2++) x2[c2] = pack2(xv[2*c2], xv[2*c2+1]);
            #pragma unroll
            for (int o = 0; o < 32; o++) {
                unsigned long long a0 = 0ull, a1 = 0ull;
                const unsigned long long* wr = (const unsigned long long*)(wks + o * 32);
                #pragma unroll
                for (int c2 = 0; c2 < 16; c2 += 2) {
                    fma2(a0, wr[c2],   x2[c2]);
                    fma2(a1, wr[c2+1], x2[c2+1]);
                }
                kA[i * STR_ + o] = sum2(add2(a0, a1)) + bks[o];
            }
        }
    }
    __syncthreads();

    // ---- banded attention + cost stream (interleaved per-warp schedule) ----
    const int warp = tid >> 5;
    const int lane = tid & 31;
    const float inv_c = 1.0f / 32.0f;
    const float* cbase = cost + (size_t)d * BHWW_ + (size_t)(b * H_ + h) * WW_;
    float*       obase = out  + (d ? (2*XN_ + BHWW_) : (2*XN_)) + (size_t)(b * H_ + h) * WW_;

    const int r0 = lane >> 3;           // 0..3
    const int c4 = (lane & 7) << 2;     // 0,4,...,28
    float* sw = scoreB + warp * 256;    // per-warp swizzled score chunk [8][32]

    #pragma unroll 1
    for (int n = 0; n < 8; n++) {
        const int e = SCHED[(warp << 3) + n];
        const int code = e & 63;
        int it = code >> 3, jt = code & 7;
        if (d) { const int tmp = it; it = jt; jt = tmp; }
        const float* cpt = cbase + (size_t)(it * 32) * W_ + jt * 32;
        float*       opt = obase + (size_t)(it * 32) * W_ + jt * 32;

        if (e & 128) {
            // ---- compute tile ----
            const int jj = jt * 32 + lane;
            unsigned long long k2[16];
            const unsigned long long* krow = (const unsigned long long*)(kA + jj * STR_);
            #pragma unroll
            for (int c2 = 0; c2 < 16; c2++) k2[c2] = krow[c2];

            float4 cv0 = __ldcs((const float4*)(cpt + (size_t)r0 * W_ + c4));
            float4 cv1 = __ldcs((const float4*)(cpt + (size_t)(r0 + 4) * W_ + c4));

            #pragma unroll
            for (int cc = 0; cc < 4; cc++) {
                // compute 8 rows of scores into swizzled smem
                #pragma unroll
                for (int rr = 0; rr < 8; rr++) {
                    const int ii = it * 32 + (cc << 3) + rr;
                    const unsigned long long* qrow = (const unsigned long long*)(qA + ii * STR_);
                    unsigned long long a0 = 0ull, a1 = 0ull, a2 = 0ull, a3 = 0ull;
                    #pragma unroll
                    for (int c2 = 0; c2 < 16; c2 += 4) {
                        fma2(a0, qrow[c2],   k2[c2]);
                        fma2(a1, qrow[c2+1], k2[c2+1]);
                        fma2(a2, qrow[c2+2], k2[c2+2]);
                        fma2(a3, qrow[c2+3], k2[c2+3]);
                    }
                    const float s = sum2(add2(add2(a0, a1), add2(a2, a3))) * inv_c;
                    const int diff = d ? (jj - ii) : (ii - jj);
                    const float sv = ((unsigned)diff < (unsigned)CR_) ? s : 0.0f;
                    // swizzled store: f4-block (lane>>2) XOR row
                    sw[(rr << 5) + ((((lane >> 2) ^ rr) & 7) << 2) + (lane & 3)] = sv;
                }
                __syncwarp();
                const float4 s0 = *(const float4*)(sw + (r0 << 5) + ((((lane & 7) ^ r0) & 7) << 2));
                const float4 s1 = *(const float4*)(sw + ((r0 + 4) << 5) + ((((lane & 7) ^ (r0 + 4)) & 7) << 2));
                __syncwarp();

                const int ra = (cc << 3) + r0;
                const int rb = ra + 4;
                float4 n0 = cv0, n1 = cv1;
                if (cc < 3) {
                    n0 = __ldcs((const float4*)(cpt + (size_t)(ra + 8) * W_ + c4));
                    n1 = __ldcs((const float4*)(cpt + (size_t)(rb + 8) * W_ + c4));
                }
                float4 o0, o1;
                o0.x = cv0.x + s0.x; o0.y = cv0.y + s0.y; o0.z = cv0.z + s0.z; o0.w = cv0.w + s0.w;
                o1.x = cv1.x + s1.x; o1.y = cv1.y + s1.y; o1.z = cv1.z + s1.z; o1.w = cv1.w + s1.w;
                __stcs((float4*)(opt + (size_t)ra * W_ + c4), o0);
                __stcs((float4*)(opt + (size_t)rb * W_ + c4), o1);
                cv0 = n0; cv1 = n1;
            }
        } else {
            // ---- pure copy tile: 8 LDG.128 in flight per lane ----
            float4 v[8];
            #pragma unroll
            for (int tt = 0; tt < 8; tt++)
                v[tt] = __ldcs((const float4*)(cpt + (size_t)((tt << 2) + r0) * W_ + c4));
            #pragma unroll
            for (int tt = 0; tt < 8; tt++)
                __stcs((float4*)(opt + (size_t)((tt << 2) + r0) * W_ + c4), v[tt]);
        }
    }
}

extern "C" void kernel_launch(void* const* d_in, const int* in_sizes, int n_in,
                              void* d_out, int out_size)
{
    (void)in_sizes; (void)n_in; (void)out_size;
    const int smem_bytes = (2 * 256 * STR_ + 2 * 1024 + 64) * sizeof(float);  // 78080
    cudaFuncSetAttribute(pab_kernel, cudaFuncAttributeMaxDynamicSharedMemorySize, smem_bytes);
    pab_kernel<<<2 * B_ * H_, 256, smem_bytes>>>(
        (const float*)d_in[0],  (const float*)d_in[1],  (const float*)d_in[2],
        (const float*)d_in[3],  (const float*)d_in[4],  (const float*)d_in[5],
        (const float*)d_in[6],  (const float*)d_in[7],  (const float*)d_in[8],
        (const float*)d_in[9],  (const float*)d_in[10], (const float*)d_in[11],
        (const float*)d_in[12], (const float*)d_in[13], (const float*)d_in[14],
        (float*)d_out);
}